// round 13
// baseline (speedup 1.0000x reference)
#include <cuda_runtime.h>
#include <cuda_fp16.h>

#define NN 100000
#define EE 1000000
#define CC 64
#define OUTC 40
#define NB 98          // ceil(NN/1024)
#define E4 (EE/4)
#define CSRG 592       // resident grid: 148 SMs x 8 blocks guaranteed by launch_bounds
#define CSRT 256
#define NTILES 6250    // NN/16
#define GEMMG 782      // ceil(NTILES/8) -> 1 tile per warp

typedef unsigned long long ull;

// ---------------- device scratch ----------------
__device__ int     g_cc[2 * NN + 4];   // [0,NN) counts ; [NN,2NN) cursors ; [2NN] barrier
__device__ int     g_rowptr[NN];
__device__ int     g_bsum[NB];
__device__ float   g_dinv[NN];         // rsqrt(deg+1), precomputed in scan phase
__device__ int2    g_edge[EE];         // {src*8 (uint4 idx), bitcast(norm)} grouped by dst
__device__ __half2 g_bufA[NN * CC / 2];
__device__ __half2 g_bufB[NN * CC / 2];
__device__ __half  g_Wt1[CC * CC];     // transposed fp16 weights [n][k]
__device__ __half  g_Wt2[CC * CC];
__device__ __half  g_Wtm1[CC * CC];
__device__ __half  g_Wtm2[OUTC * CC];

// ---------------- f32x2 helpers ----------------
__device__ __forceinline__ ull pack2(float v) {
    ull r; asm("mov.b64 %0, {%1, %1};" : "=l"(r) : "f"(v)); return r;
}
__device__ __forceinline__ void fma2(ull& d, ull a, ull b) {
    asm("fma.rn.f32x2 %0, %1, %2, %0;" : "+l"(d) : "l"(a), "l"(b));
}
__device__ __forceinline__ void unpack2(ull v, float& lo, float& hi) {
    asm("mov.b64 {%0, %1}, %2;" : "=f"(lo), "=f"(hi) : "l"(v));
}
__device__ __forceinline__ ull h2f2(__half2 h) {
    float2 f = __half22float2(h);
    ull r; asm("mov.b64 %0, {%1, %2};" : "=l"(r) : "f"(f.x), "f"(f.y));
    return r;
}
__device__ __forceinline__ void acc_row(ull& a0, ull& a1, ull& a2, ull& a3,
                                        uint4 v, ull n) {
    const __half2* hp = (const __half2*)&v;
    fma2(a0, h2f2(hp[0]), n);
    fma2(a1, h2f2(hp[1]), n);
    fma2(a2, h2f2(hp[2]), n);
    fma2(a3, h2f2(hp[3]), n);
}

// ---------------- prep: x fp32->fp16 rows ----------------
__global__ __launch_bounds__(256)
void k_cvtx(const float* __restrict__ x, __half2* __restrict__ out) {
    int i = blockIdx.x * 256 + threadIdx.x;   // one uint4 (8 halfs) per thread
    const float4* x4 = (const float4*)x;
    float4 f0 = x4[2 * i], f1 = x4[2 * i + 1];
    __half2 h0 = __floats2half2_rn(f0.x, f0.y);
    __half2 h1 = __floats2half2_rn(f0.z, f0.w);
    __half2 h2 = __floats2half2_rn(f1.x, f1.y);
    __half2 h3 = __floats2half2_rn(f1.z, f1.w);
    uint4 o;
    o.x = *(unsigned*)&h0; o.y = *(unsigned*)&h1;
    o.z = *(unsigned*)&h2; o.w = *(unsigned*)&h3;
    ((uint4*)out)[i] = o;
}

// ---------------- prep: weight transpose fp32->fp16 ----------------
__global__ __launch_bounds__(256)
void k_wprep(const float* __restrict__ W1, const float* __restrict__ W2,
             const float* __restrict__ Wm1, const float* __restrict__ Wm2) {
    int which = blockIdx.x, tid = threadIdx.x;
    if (which < 3) {
        const float* W = (which == 0) ? W1 : (which == 1) ? W2 : Wm1;
        __half* Wt = (which == 0) ? g_Wt1 : (which == 1) ? g_Wt2 : g_Wtm1;
        for (int i = tid; i < CC * CC; i += 256) {
            int n = i >> 6, k = i & 63;
            Wt[i] = __float2half(W[k * CC + n]);
        }
    } else {
        for (int i = tid; i < OUTC * CC; i += 256) {
            int n = i >> 6, k = i & 63;
            g_Wtm2[i] = __float2half(Wm2[k * OUTC + n]);
        }
    }
}

// ---------------- fused CSR build: hist -> scan -> fill, one kernel ----------------
__device__ __forceinline__ void gsync(int target) {
    __threadfence();
    __syncthreads();
    if (threadIdx.x == 0) {
        atomicAdd(&g_cc[2 * NN], 1);
        while (atomicAdd(&g_cc[2 * NN], 0) < target) __nanosleep(64);
        __threadfence();
    }
    __syncthreads();
}

__device__ __forceinline__ void fill_one(int s, int d) {
    float nm = g_dinv[s] * g_dinv[d];
    int pos = g_rowptr[d] + g_bsum[d >> 10] + atomicAdd(&g_cc[NN + d], 1);
    g_edge[pos] = make_int2(s * 8, __float_as_int(nm));
}

__global__ __launch_bounds__(CSRT, 8)
void k_csr(const void* __restrict__ ei) {
    __shared__ int s_is64;
    __shared__ int s_scan[CSRT];
    int tid = threadIdx.x, bid = blockIdx.x;

    if (tid == 0) {
        const long long* p = (const long long*)ei;
        int ok = 1;
#pragma unroll
        for (int i = 0; i < 16; i++) { long long v = p[i]; if (v < 0 || v >= NN) ok = 0; }
        s_is64 = ok;
    }
    __syncthreads();
    int is64 = s_is64;

    // Phase A: degree histogram
    for (int i = bid * CSRT + tid; i < E4; i += CSRG * CSRT) {
        if (!is64) {
            int4 d = ((const int4*)ei)[E4 + i];
            atomicAdd(&g_cc[d.x], 1); atomicAdd(&g_cc[d.y], 1);
            atomicAdd(&g_cc[d.z], 1); atomicAdd(&g_cc[d.w], 1);
        } else {
            const long long* p = (const long long*)ei;
#pragma unroll
            for (int j = 0; j < 4; j++) atomicAdd(&g_cc[(int)p[EE + 4 * i + j]], 1);
        }
    }
    gsync(CSRG);

    // Phase B: per-1024-node exclusive scan + dinv precompute
    if (bid < NB) {
        int base = bid * 1024 + tid * 4;
        int c0 = 0, c1 = 0, c2 = 0, c3 = 0;
        if (base + 0 < NN) c0 = g_cc[base + 0];
        if (base + 1 < NN) c1 = g_cc[base + 1];
        if (base + 2 < NN) c2 = g_cc[base + 2];
        if (base + 3 < NN) c3 = g_cc[base + 3];
        if (base + 0 < NN) g_dinv[base + 0] = rsqrtf((float)c0 + 1.0f);
        if (base + 1 < NN) g_dinv[base + 1] = rsqrtf((float)c1 + 1.0f);
        if (base + 2 < NN) g_dinv[base + 2] = rsqrtf((float)c2 + 1.0f);
        if (base + 3 < NN) g_dinv[base + 3] = rsqrtf((float)c3 + 1.0f);
        int v = c0 + c1 + c2 + c3;
        s_scan[tid] = v;
        __syncthreads();
        for (int off = 1; off < CSRT; off <<= 1) {
            int t2 = (tid >= off) ? s_scan[tid - off] : 0;
            __syncthreads();
            s_scan[tid] += t2;
            __syncthreads();
        }
        int incl = s_scan[tid];
        int excl = incl - v;
        if (base + 0 < NN) g_rowptr[base + 0] = excl;
        if (base + 1 < NN) g_rowptr[base + 1] = excl + c0;
        if (base + 2 < NN) g_rowptr[base + 2] = excl + c0 + c1;
        if (base + 3 < NN) g_rowptr[base + 3] = excl + c0 + c1 + c2;
        if (tid == CSRT - 1) g_bsum[bid] = incl;
    }
    gsync(2 * CSRG);

    // Phase C: block 0 exclusive-scans the NB block sums
    if (bid == 0) {
        int lane = tid & 31, w = tid >> 5;
        int v = (tid < NB) ? g_bsum[tid] : 0;
        int x = v;
#pragma unroll
        for (int off = 1; off < 32; off <<= 1) {
            int y = __shfl_up_sync(0xffffffffu, x, off);
            if (lane >= off) x += y;
        }
        if (lane == 31 && w < 4) s_scan[w] = x;
        __syncthreads();
        if (tid < NB) {
            int woff = 0;
#pragma unroll
            for (int q = 0; q < 4; q++) if (q < w) woff += s_scan[q];
            g_bsum[tid] = x - v + woff;
        }
    }
    gsync(3 * CSRG);

    // Phase D: fill edge records
    for (int i = bid * CSRT + tid; i < E4; i += CSRG * CSRT) {
        if (!is64) {
            int4 s4 = ((const int4*)ei)[i];
            int4 d4 = ((const int4*)ei)[E4 + i];
            fill_one(s4.x, d4.x); fill_one(s4.y, d4.y);
            fill_one(s4.z, d4.z); fill_one(s4.w, d4.w);
        } else {
            const long long* p = (const long long*)ei;
#pragma unroll
            for (int j = 0; j < 4; j++)
                fill_one((int)p[4 * i + j], (int)p[EE + 4 * i + j]);
        }
    }
}

// ---------------- tensor-core GEMM with smem + ldmatrix ----------------
__device__ __forceinline__ unsigned scvt(const void* p) {
    return (unsigned)__cvta_generic_to_shared(p);
}
__device__ __forceinline__ void ldsm4(unsigned& r0, unsigned& r1, unsigned& r2,
                                      unsigned& r3, unsigned addr) {
    asm volatile("ldmatrix.sync.aligned.m8n8.x4.shared.b16 {%0,%1,%2,%3}, [%4];"
                 : "=r"(r0), "=r"(r1), "=r"(r2), "=r"(r3) : "r"(addr));
}
__device__ __forceinline__ void ldsm2(unsigned& r0, unsigned& r1, unsigned addr) {
    asm volatile("ldmatrix.sync.aligned.m8n8.x2.shared.b16 {%0,%1}, [%2];"
                 : "=r"(r0), "=r"(r1) : "r"(addr));
}
__device__ __forceinline__ void mma16816(float c[4], unsigned a0, unsigned a1,
                                         unsigned a2, unsigned a3,
                                         unsigned b0, unsigned b1) {
    asm volatile(
        "mma.sync.aligned.m16n8k16.row.col.f32.f16.f16.f32 "
        "{%0,%1,%2,%3},{%4,%5,%6,%7},{%8,%9},{%0,%1,%2,%3};"
        : "+f"(c[0]), "+f"(c[1]), "+f"(c[2]), "+f"(c[3])
        : "r"(a0), "r"(a1), "r"(a2), "r"(a3), "r"(b0), "r"(b1));
}

// out[N, NT*8] = A[N,64](f16) @ Wt^T ; f32 accum. One 16-row tile per warp.
template <int NT, bool BIAS, bool RELU, bool OUTF32>
__global__ __launch_bounds__(256)
void k_gemmTC(const __half* __restrict__ A, const __half* __restrict__ Wt,
              const float* __restrict__ bias, void* __restrict__ outv) {
    const int NCOLS = NT * 8;
    __shared__ uint4 Bs[NT * 8 * 8];      // NT*8 rows x 8 swizzled 16B chunks
    __shared__ uint4 As[8][128];          // per-warp 16 rows x 8 swizzled chunks
    int tid = threadIdx.x, lane = tid & 31, wid = tid >> 5;

    const uint4* W4 = (const uint4*)Wt;
    for (int i = tid; i < NT * 64; i += 256) {
        int r = i >> 3, c = i & 7;
        Bs[r * 8 + (c ^ (r & 7))] = W4[i];
    }
    __syncthreads();

    int tile = blockIdx.x * 8 + wid;
    if (tile >= NTILES) return;

    const uint4* A4 = (const uint4*)(A + (size_t)tile * 16 * CC);
#pragma unroll
    for (int j = 0; j < 4; j++) {
        int i = j * 32 + lane;
        int r = i >> 3, c = i & 7;
        As[wid][r * 8 + (c ^ (r & 7))] = A4[i];
    }
    __syncwarp();

    int ri = lane & 7, m = lane >> 3;
    float c_[NT][4];
#pragma unroll
    for (int nt = 0; nt < NT; nt++) { c_[nt][0] = c_[nt][1] = c_[nt][2] = c_[nt][3] = 0.f; }

#pragma unroll
    for (int ks = 0; ks < 4; ks++) {
        int ar = (m & 1) ? (8 + ri) : ri;
        int ac = 2 * ks + (m >> 1);
        unsigned a0, a1, a2, a3;
        ldsm4(a0, a1, a2, a3, scvt(&As[wid][ar * 8 + (ac ^ (ar & 7))]));

        unsigned b[NT][2];
#pragma unroll
        for (int ntp = 0; ntp < NT / 2; ntp++) {
            int br = 16 * ntp + ((m >> 1) ? 8 : 0) + ri;
            int bc = 2 * ks + (m & 1);
            unsigned r0, r1, r2, r3;
            ldsm4(r0, r1, r2, r3, scvt(&Bs[br * 8 + (bc ^ (br & 7))]));
            b[2 * ntp][0] = r0; b[2 * ntp][1] = r1;
            b[2 * ntp + 1][0] = r2; b[2 * ntp + 1][1] = r3;
        }
        if (NT & 1) {
            int m2 = m & 1;
            int br = (NT - 1) * 8 + ri;
            int bc = 2 * ks + m2;
            unsigned r0, r1;
            ldsm2(r0, r1, scvt(&Bs[br * 8 + (bc ^ (br & 7))]));
            b[NT - 1][0] = r0; b[NT - 1][1] = r1;
        }

#pragma unroll
        for (int nt = 0; nt < NT; nt++)
            mma16816(c_[nt], a0, a1, a2, a3, b[nt][0], b[nt][1]);
    }

    int g = lane >> 2, t = lane & 3;
    int r0 = tile * 16 + g;
#pragma unroll
    for (int nt = 0; nt < NT; nt++) {
        int col = nt * 8 + 2 * t;
        float c0 = c_[nt][0], c1 = c_[nt][1], c2 = c_[nt][2], c3 = c_[nt][3];
        if (BIAS) {
            float bb0 = __ldg(bias + col), bb1 = __ldg(bias + col + 1);
            c0 += bb0; c1 += bb1; c2 += bb0; c3 += bb1;
        }
        if (RELU) {
            c0 = fmaxf(c0, 0.f); c1 = fmaxf(c1, 0.f);
            c2 = fmaxf(c2, 0.f); c3 = fmaxf(c3, 0.f);
        }
        if (OUTF32) {
            float* o = (float*)outv;
            *(float2*)(o + (size_t)r0 * NCOLS + col)       = make_float2(c0, c1);
            *(float2*)(o + (size_t)(r0 + 8) * NCOLS + col) = make_float2(c2, c3);
        } else {
            __half* o = (__half*)outv;
            *(__half2*)(o + (size_t)r0 * NCOLS + col)       = __floats2half2_rn(c0, c1);
            *(__half2*)(o + (size_t)(r0 + 8) * NCOLS + col) = __floats2half2_rn(c2, c3);
        }
    }
}

// ---------------- aggregation: 4 nodes/warp, 8 lanes/node, f32x2 accum, unroll 4 ----------------
template <bool RELU>
__global__ __launch_bounds__(256)
void k_agg(const __half2* __restrict__ hf, const float* __restrict__ bias,
           __half2* __restrict__ out) {
    const uint4* hf4 = (const uint4*)hf;
    int node = blockIdx.x * 32 + (threadIdx.x >> 3);
    int l = threadIdx.x & 7;

    int deg = g_cc[node];
    float self = __frcp_rn((float)deg + 1.0f);   // dinv^2

    ull a0 = 0, a1 = 0, a2 = 0, a3 = 0;
    acc_row(a0, a1, a2, a3, hf4[node * 8 + l], pack2(self));

    int beg = g_rowptr[node] + g_bsum[node >> 10];
    int end = (node + 1 == NN) ? EE : (g_rowptr[node + 1] + g_bsum[(node + 1) >> 10]);

    int e = beg;
    for (; e + 3 < end; e += 4) {
        int2 m0 = g_edge[e],     m1 = g_edge[e + 1];
        int2 m2 = g_edge[e + 2], m3 = g_edge[e + 3];
        uint4 v0 = hf4[m0.x + l];
        uint4 v1 = hf4[m1.x + l];
        uint4 v2 = hf4[m2.x + l];
        uint4 v3 = hf4[m3.x + l];
        acc_row(a0, a1, a2, a3, v0, pack2(__int_as_float(m0.y)));
        acc_row(a0, a1, a2, a3, v1, pack2(__int_as_float(m1.y)));
        acc_row(a0, a1, a2, a3, v2, pack2(__int_as_float(m2.y)));
        acc_row(a0, a1, a2, a3, v3, pack2(__int_as_float(m3.y)));
    }
    for (; e < end; e++) {
        int2 m = g_edge[e];
        acc_row(a0, a1, a2, a3, hf4[m.x + l], pack2(__int_as_float(m.y)));
    }

    float f0, f1, f2, f3, f4, f5, f6, f7;
    unpack2(a0, f0, f1); unpack2(a1, f2, f3);
    unpack2(a2, f4, f5); unpack2(a3, f6, f7);

    const float4* b4 = (const float4*)(bias + l * 8);
    float4 bA = b4[0], bB = b4[1];
    f0 += bA.x; f1 += bA.y; f2 += bA.z; f3 += bA.w;
    f4 += bB.x; f5 += bB.y; f6 += bB.z; f7 += bB.w;
    if (RELU) {
        f0 = fmaxf(f0, 0.f); f1 = fmaxf(f1, 0.f);
        f2 = fmaxf(f2, 0.f); f3 = fmaxf(f3, 0.f);
        f4 = fmaxf(f4, 0.f); f5 = fmaxf(f5, 0.f);
        f6 = fmaxf(f6, 0.f); f7 = fmaxf(f7, 0.f);
    }
    __half2 h0 = __floats2half2_rn(f0, f1);
    __half2 h1 = __floats2half2_rn(f2, f3);
    __half2 h2 = __floats2half2_rn(f4, f5);
    __half2 h3 = __floats2half2_rn(f6, f7);
    uint4 o;
    o.x = *(unsigned*)&h0; o.y = *(unsigned*)&h1;
    o.z = *(unsigned*)&h2; o.w = *(unsigned*)&h3;
    ((uint4*)out)[node * 8 + l] = o;
}

// ---------------- launcher ----------------
extern "C" void kernel_launch(void* const* d_in, const int* in_sizes, int n_in,
                              void* d_out, int out_size) {
    const float* x   = (const float*)d_in[0];
    const void*  ei  = d_in[1];
    const float* W1  = (const float*)d_in[2];
    const float* b1  = (const float*)d_in[3];
    const float* W2  = (const float*)d_in[4];
    const float* b2  = (const float*)d_in[5];
    const float* Wm1 = (const float*)d_in[6];
    const float* bm1 = (const float*)d_in[7];
    const float* Wm2 = (const float*)d_in[8];
    const float* bm2 = (const float*)d_in[9];
    float* out = (float*)d_out;

    void *pcc = nullptr, *pa = nullptr, *pb = nullptr;
    void *pw1 = nullptr, *pw2 = nullptr, *pm1 = nullptr, *pm2 = nullptr;
    cudaGetSymbolAddress(&pcc, g_cc);
    cudaGetSymbolAddress(&pa, g_bufA);
    cudaGetSymbolAddress(&pb, g_bufB);
    cudaGetSymbolAddress(&pw1, g_Wt1);
    cudaGetSymbolAddress(&pw2, g_Wt2);
    cudaGetSymbolAddress(&pm1, g_Wtm1);
    cudaGetSymbolAddress(&pm2, g_Wtm2);
    __half2* bufA = (__half2*)pa;
    __half2* bufB = (__half2*)pb;
    const __half* Wt1  = (const __half*)pw1;
    const __half* Wt2  = (const __half*)pw2;
    const __half* Wtm1 = (const __half*)pm1;
    const __half* Wtm2 = (const __half*)pm2;

    cudaMemsetAsync(pcc, 0, (2 * NN + 4) * sizeof(int));

    k_cvtx <<<3125, 256>>>(x, bufA);                                        // 1
    k_wprep<<<4, 256>>>(W1, W2, Wm1, Wm2);                                  // 2
    k_gemmTC<8, false, false, false><<<GEMMG, 256>>>((const __half*)bufA, Wt1, nullptr, bufB);   // 3
    k_csr <<<CSRG, CSRT>>>(ei);                                             // 4: PROFILED
    k_agg<true><<<3125, 256>>>(bufB, b1, bufA);                             // 5
    k_gemmTC<8, false, false, false><<<GEMMG, 256>>>((const __half*)bufA, Wt2, nullptr, bufB);   // 6
    k_agg<false><<<3125, 256>>>(bufB, b2, bufA);                            // 7
    k_gemmTC<8, true, true, false><<<GEMMG, 256>>>((const __half*)bufA, Wtm1, bm1, bufB);        // 8
    k_gemmTC<5, true, false, true><<<GEMMG, 256>>>((const __half*)bufB, Wtm2, bm2, out);         // 9
}

// round 14
// speedup vs baseline: 1.1250x; 1.1250x over previous
#include <cuda_runtime.h>
#include <cuda_fp16.h>

#define NN 100000
#define EE 1000000
#define CC 64
#define OUTC 40
#define NB 98          // ceil(NN/1024)
#define E4 (EE/4)
#define CSRG 592       // resident grid: 148 SMs x 8 blocks guaranteed by launch_bounds
#define CSRT 256
#define NTILES 6250    // NN/16
#define GEMMG 782      // ceil(NTILES/8) -> 1 tile per warp

typedef unsigned long long ull;

// ---------------- device scratch ----------------
__device__ int     g_cc[2 * NN + 4];   // [0,NN) counts ; [NN,2NN) cursors ; [2NN] barrier ; [2NN+1] offset ctr
__device__ int     g_rowptr[NN];       // ABSOLUTE row start (block offsets via atomic)
__device__ float   g_dinv[NN];         // rsqrt(deg+1), precomputed in scan phase
__device__ int2    g_edge[EE];         // {src*8 (uint4 idx), bitcast(norm)} grouped by dst
__device__ __half2 g_bufA[NN * CC / 2];
__device__ __half2 g_bufB[NN * CC / 2];
__device__ __half  g_Wt1[CC * CC];     // transposed fp16 weights [n][k]
__device__ __half  g_Wt2[CC * CC];
__device__ __half  g_Wtm1[CC * CC];
__device__ __half  g_Wtm2[OUTC * CC];

// ---------------- prep: x fp32->fp16 rows ----------------
__global__ __launch_bounds__(256)
void k_cvtx(const float* __restrict__ x, __half2* __restrict__ out) {
    int i = blockIdx.x * 256 + threadIdx.x;   // one uint4 (8 halfs) per thread
    const float4* x4 = (const float4*)x;
    float4 f0 = x4[2 * i], f1 = x4[2 * i + 1];
    __half2 h0 = __floats2half2_rn(f0.x, f0.y);
    __half2 h1 = __floats2half2_rn(f0.z, f0.w);
    __half2 h2 = __floats2half2_rn(f1.x, f1.y);
    __half2 h3 = __floats2half2_rn(f1.z, f1.w);
    uint4 o;
    o.x = *(unsigned*)&h0; o.y = *(unsigned*)&h1;
    o.z = *(unsigned*)&h2; o.w = *(unsigned*)&h3;
    ((uint4*)out)[i] = o;
}

// ---------------- prep: weight transpose fp32->fp16 ----------------
__global__ __launch_bounds__(256)
void k_wprep(const float* __restrict__ W1, const float* __restrict__ W2,
             const float* __restrict__ Wm1, const float* __restrict__ Wm2) {
    int which = blockIdx.x, tid = threadIdx.x;
    if (which < 3) {
        const float* W = (which == 0) ? W1 : (which == 1) ? W2 : Wm1;
        __half* Wt = (which == 0) ? g_Wt1 : (which == 1) ? g_Wt2 : g_Wtm1;
        for (int i = tid; i < CC * CC; i += 256) {
            int n = i >> 6, k = i & 63;
            Wt[i] = __float2half(W[k * CC + n]);
        }
    } else {
        for (int i = tid; i < OUTC * CC; i += 256) {
            int n = i >> 6, k = i & 63;
            g_Wtm2[i] = __float2half(Wm2[k * OUTC + n]);
        }
    }
}

// ---------------- fused CSR build: hist -> scan(+atomic offsets) -> fill ----------------
__device__ __forceinline__ void gsync(int target) {
    __threadfence();
    __syncthreads();
    if (threadIdx.x == 0) {
        atomicAdd(&g_cc[2 * NN], 1);
        while (atomicAdd(&g_cc[2 * NN], 0) < target) __nanosleep(64);
        __threadfence();
    }
    __syncthreads();
}

__device__ __forceinline__ void fill_one(int s, int d) {
    float nm = g_dinv[s] * g_dinv[d];
    int pos = g_rowptr[d] + atomicAdd(&g_cc[NN + d], 1);
    g_edge[pos] = make_int2(s * 8, __float_as_int(nm));
}

__global__ __launch_bounds__(CSRT, 8)
void k_csr(const void* __restrict__ ei) {
    __shared__ int s_is64;
    __shared__ int s_scan[CSRT];
    __shared__ int s_off;
    int tid = threadIdx.x, bid = blockIdx.x;

    if (tid == 0) {
        const long long* p = (const long long*)ei;
        int ok = 1;
#pragma unroll
        for (int i = 0; i < 16; i++) { long long v = p[i]; if (v < 0 || v >= NN) ok = 0; }
        s_is64 = ok;
    }
    __syncthreads();
    int is64 = s_is64;

    // Phase A: degree histogram
    for (int i = bid * CSRT + tid; i < E4; i += CSRG * CSRT) {
        if (!is64) {
            int4 d = ((const int4*)ei)[E4 + i];
            atomicAdd(&g_cc[d.x], 1); atomicAdd(&g_cc[d.y], 1);
            atomicAdd(&g_cc[d.z], 1); atomicAdd(&g_cc[d.w], 1);
        } else {
            const long long* p = (const long long*)ei;
#pragma unroll
            for (int j = 0; j < 4; j++) atomicAdd(&g_cc[(int)p[EE + 4 * i + j]], 1);
        }
    }
    gsync(CSRG);

    // Phase B: per-1024-node scan; block offset claimed by global atomic -> ABSOLUTE rowptr
    if (bid < NB) {
        int base = bid * 1024 + tid * 4;
        int c0 = 0, c1 = 0, c2 = 0, c3 = 0;
        if (base + 0 < NN) c0 = g_cc[base + 0];
        if (base + 1 < NN) c1 = g_cc[base + 1];
        if (base + 2 < NN) c2 = g_cc[base + 2];
        if (base + 3 < NN) c3 = g_cc[base + 3];
        if (base + 0 < NN) g_dinv[base + 0] = rsqrtf((float)c0 + 1.0f);
        if (base + 1 < NN) g_dinv[base + 1] = rsqrtf((float)c1 + 1.0f);
        if (base + 2 < NN) g_dinv[base + 2] = rsqrtf((float)c2 + 1.0f);
        if (base + 3 < NN) g_dinv[base + 3] = rsqrtf((float)c3 + 1.0f);
        int v = c0 + c1 + c2 + c3;
        s_scan[tid] = v;
        __syncthreads();
        for (int off = 1; off < CSRT; off <<= 1) {
            int t2 = (tid >= off) ? s_scan[tid - off] : 0;
            __syncthreads();
            s_scan[tid] += t2;
            __syncthreads();
        }
        int incl = s_scan[tid];
        int excl = incl - v;
        if (tid == CSRT - 1) s_off = atomicAdd(&g_cc[2 * NN + 1], incl);
        __syncthreads();
        int boff = s_off;
        if (base + 0 < NN) g_rowptr[base + 0] = boff + excl;
        if (base + 1 < NN) g_rowptr[base + 1] = boff + excl + c0;
        if (base + 2 < NN) g_rowptr[base + 2] = boff + excl + c0 + c1;
        if (base + 3 < NN) g_rowptr[base + 3] = boff + excl + c0 + c1 + c2;
    }
    gsync(2 * CSRG);

    // Phase C: fill edge records
    for (int i = bid * CSRT + tid; i < E4; i += CSRG * CSRT) {
        if (!is64) {
            int4 s4 = ((const int4*)ei)[i];
            int4 d4 = ((const int4*)ei)[E4 + i];
            fill_one(s4.x, d4.x); fill_one(s4.y, d4.y);
            fill_one(s4.z, d4.z); fill_one(s4.w, d4.w);
        } else {
            const long long* p = (const long long*)ei;
#pragma unroll
            for (int j = 0; j < 4; j++)
                fill_one((int)p[4 * i + j], (int)p[EE + 4 * i + j]);
        }
    }
}

// ---------------- tensor-core GEMM with smem + ldmatrix ----------------
__device__ __forceinline__ unsigned scvt(const void* p) {
    return (unsigned)__cvta_generic_to_shared(p);
}
__device__ __forceinline__ void ldsm4(unsigned& r0, unsigned& r1, unsigned& r2,
                                      unsigned& r3, unsigned addr) {
    asm volatile("ldmatrix.sync.aligned.m8n8.x4.shared.b16 {%0,%1,%2,%3}, [%4];"
                 : "=r"(r0), "=r"(r1), "=r"(r2), "=r"(r3) : "r"(addr));
}
__device__ __forceinline__ void ldsm2(unsigned& r0, unsigned& r1, unsigned addr) {
    asm volatile("ldmatrix.sync.aligned.m8n8.x2.shared.b16 {%0,%1}, [%2];"
                 : "=r"(r0), "=r"(r1) : "r"(addr));
}
__device__ __forceinline__ void mma16816(float c[4], unsigned a0, unsigned a1,
                                         unsigned a2, unsigned a3,
                                         unsigned b0, unsigned b1) {
    asm volatile(
        "mma.sync.aligned.m16n8k16.row.col.f32.f16.f16.f32 "
        "{%0,%1,%2,%3},{%4,%5,%6,%7},{%8,%9},{%0,%1,%2,%3};"
        : "+f"(c[0]), "+f"(c[1]), "+f"(c[2]), "+f"(c[3])
        : "r"(a0), "r"(a1), "r"(a2), "r"(a3), "r"(b0), "r"(b1));
}

// out[N, NT*8] = A[N,64](f16) @ Wt^T ; f32 accum. One 16-row tile per warp.
template <int NT, bool BIAS, bool RELU, bool OUTF32>
__global__ __launch_bounds__(256)
void k_gemmTC(const __half* __restrict__ A, const __half* __restrict__ Wt,
              const float* __restrict__ bias, void* __restrict__ outv) {
    const int NCOLS = NT * 8;
    __shared__ uint4 Bs[NT * 8 * 8];      // NT*8 rows x 8 swizzled 16B chunks
    __shared__ uint4 As[8][128];          // per-warp 16 rows x 8 swizzled chunks
    int tid = threadIdx.x, lane = tid & 31, wid = tid >> 5;

    const uint4* W4 = (const uint4*)Wt;
    for (int i = tid; i < NT * 64; i += 256) {
        int r = i >> 3, c = i & 7;
        Bs[r * 8 + (c ^ (r & 7))] = W4[i];
    }
    __syncthreads();

    int tile = blockIdx.x * 8 + wid;
    if (tile >= NTILES) return;

    const uint4* A4 = (const uint4*)(A + (size_t)tile * 16 * CC);
#pragma unroll
    for (int j = 0; j < 4; j++) {
        int i = j * 32 + lane;
        int r = i >> 3, c = i & 7;
        As[wid][r * 8 + (c ^ (r & 7))] = A4[i];
    }
    __syncwarp();

    int ri = lane & 7, m = lane >> 3;
    float c_[NT][4];
#pragma unroll
    for (int nt = 0; nt < NT; nt++) { c_[nt][0] = c_[nt][1] = c_[nt][2] = c_[nt][3] = 0.f; }

#pragma unroll
    for (int ks = 0; ks < 4; ks++) {
        int ar = (m & 1) ? (8 + ri) : ri;
        int ac = 2 * ks + (m >> 1);
        unsigned a0, a1, a2, a3;
        ldsm4(a0, a1, a2, a3, scvt(&As[wid][ar * 8 + (ac ^ (ar & 7))]));

        unsigned b[NT][2];
#pragma unroll
        for (int ntp = 0; ntp < NT / 2; ntp++) {
            int br = 16 * ntp + ((m >> 1) ? 8 : 0) + ri;
            int bc = 2 * ks + (m & 1);
            unsigned r0, r1, r2, r3;
            ldsm4(r0, r1, r2, r3, scvt(&Bs[br * 8 + (bc ^ (br & 7))]));
            b[2 * ntp][0] = r0; b[2 * ntp][1] = r1;
            b[2 * ntp + 1][0] = r2; b[2 * ntp + 1][1] = r3;
        }
        if (NT & 1) {
            int m2 = m & 1;
            int br = (NT - 1) * 8 + ri;
            int bc = 2 * ks + m2;
            unsigned r0, r1;
            ldsm2(r0, r1, scvt(&Bs[br * 8 + (bc ^ (br & 7))]));
            b[NT - 1][0] = r0; b[NT - 1][1] = r1;
        }

#pragma unroll
        for (int nt = 0; nt < NT; nt++)
            mma16816(c_[nt], a0, a1, a2, a3, b[nt][0], b[nt][1]);
    }

    int g = lane >> 2, t = lane & 3;
    int r0 = tile * 16 + g;
#pragma unroll
    for (int nt = 0; nt < NT; nt++) {
        int col = nt * 8 + 2 * t;
        float c0 = c_[nt][0], c1 = c_[nt][1], c2 = c_[nt][2], c3 = c_[nt][3];
        if (BIAS) {
            float bb0 = __ldg(bias + col), bb1 = __ldg(bias + col + 1);
            c0 += bb0; c1 += bb1; c2 += bb0; c3 += bb1;
        }
        if (RELU) {
            c0 = fmaxf(c0, 0.f); c1 = fmaxf(c1, 0.f);
            c2 = fmaxf(c2, 0.f); c3 = fmaxf(c3, 0.f);
        }
        if (OUTF32) {
            float* o = (float*)outv;
            *(float2*)(o + (size_t)r0 * NCOLS + col)       = make_float2(c0, c1);
            *(float2*)(o + (size_t)(r0 + 8) * NCOLS + col) = make_float2(c2, c3);
        } else {
            __half* o = (__half*)outv;
            *(__half2*)(o + (size_t)r0 * NCOLS + col)       = __floats2half2_rn(c0, c1);
            *(__half2*)(o + (size_t)(r0 + 8) * NCOLS + col) = __floats2half2_rn(c2, c3);
        }
    }
}

// ---------------- aggregation: 4 nodes/warp, 8 lanes/node (R12 form) ----------------
template <bool RELU>
__global__ __launch_bounds__(256)
void k_agg(const __half2* __restrict__ hf, const float* __restrict__ bias,
           __half2* __restrict__ out) {
    const uint4* hf4 = (const uint4*)hf;
    int node = blockIdx.x * 32 + (threadIdx.x >> 3);
    int l = threadIdx.x & 7;

    int deg = g_cc[node];
    float self = __frcp_rn((float)deg + 1.0f);   // dinv^2

    float a0, a1, a2, a3, a4, a5, a6, a7;
    {
        uint4 v = hf4[node * 8 + l];
        const __half2* hp = (const __half2*)&v;
        float2 f0 = __half22float2(hp[0]), f1 = __half22float2(hp[1]);
        float2 f2 = __half22float2(hp[2]), f3 = __half22float2(hp[3]);
        a0 = f0.x * self; a1 = f0.y * self;
        a2 = f1.x * self; a3 = f1.y * self;
        a4 = f2.x * self; a5 = f2.y * self;
        a6 = f3.x * self; a7 = f3.y * self;
    }

    int beg = g_rowptr[node];
    int end = beg + deg;

    int e = beg;
    for (; e + 1 < end; e += 2) {
        int2 m0 = g_edge[e], m1 = g_edge[e + 1];
        uint4 v0 = hf4[m0.x + l];
        uint4 v1 = hf4[m1.x + l];
        float n0 = __int_as_float(m0.y);
        float n1 = __int_as_float(m1.y);
        {
            const __half2* hp = (const __half2*)&v0;
            float2 f0 = __half22float2(hp[0]), f1 = __half22float2(hp[1]);
            float2 f2 = __half22float2(hp[2]), f3 = __half22float2(hp[3]);
            a0 = fmaf(f0.x, n0, a0); a1 = fmaf(f0.y, n0, a1);
            a2 = fmaf(f1.x, n0, a2); a3 = fmaf(f1.y, n0, a3);
            a4 = fmaf(f2.x, n0, a4); a5 = fmaf(f2.y, n0, a5);
            a6 = fmaf(f3.x, n0, a6); a7 = fmaf(f3.y, n0, a7);
        }
        {
            const __half2* hp = (const __half2*)&v1;
            float2 f0 = __half22float2(hp[0]), f1 = __half22float2(hp[1]);
            float2 f2 = __half22float2(hp[2]), f3 = __half22float2(hp[3]);
            a0 = fmaf(f0.x, n1, a0); a1 = fmaf(f0.y, n1, a1);
            a2 = fmaf(f1.x, n1, a2); a3 = fmaf(f1.y, n1, a3);
            a4 = fmaf(f2.x, n1, a4); a5 = fmaf(f2.y, n1, a5);
            a6 = fmaf(f3.x, n1, a6); a7 = fmaf(f3.y, n1, a7);
        }
    }
    if (e < end) {
        int2 m = g_edge[e];
        uint4 v = hf4[m.x + l];
        float nm = __int_as_float(m.y);
        const __half2* hp = (const __half2*)&v;
        float2 f0 = __half22float2(hp[0]), f1 = __half22float2(hp[1]);
        float2 f2 = __half22float2(hp[2]), f3 = __half22float2(hp[3]);
        a0 = fmaf(f0.x, nm, a0); a1 = fmaf(f0.y, nm, a1);
        a2 = fmaf(f1.x, nm, a2); a3 = fmaf(f1.y, nm, a3);
        a4 = fmaf(f2.x, nm, a4); a5 = fmaf(f2.y, nm, a5);
        a6 = fmaf(f3.x, nm, a6); a7 = fmaf(f3.y, nm, a7);
    }

    const float4* b4 = (const float4*)(bias + l * 8);
    float4 bA = b4[0], bB = b4[1];
    a0 += bA.x; a1 += bA.y; a2 += bA.z; a3 += bA.w;
    a4 += bB.x; a5 += bB.y; a6 += bB.z; a7 += bB.w;
    if (RELU) {
        a0 = fmaxf(a0, 0.f); a1 = fmaxf(a1, 0.f);
        a2 = fmaxf(a2, 0.f); a3 = fmaxf(a3, 0.f);
        a4 = fmaxf(a4, 0.f); a5 = fmaxf(a5, 0.f);
        a6 = fmaxf(a6, 0.f); a7 = fmaxf(a7, 0.f);
    }
    __half2 h0 = __floats2half2_rn(a0, a1);
    __half2 h1 = __floats2half2_rn(a2, a3);
    __half2 h2 = __floats2half2_rn(a4, a5);
    __half2 h3 = __floats2half2_rn(a6, a7);
    uint4 o;
    o.x = *(unsigned*)&h0; o.y = *(unsigned*)&h1;
    o.z = *(unsigned*)&h2; o.w = *(unsigned*)&h3;
    ((uint4*)out)[node * 8 + l] = o;
}

// ---------------- launcher ----------------
extern "C" void kernel_launch(void* const* d_in, const int* in_sizes, int n_in,
                              void* d_out, int out_size) {
    const float* x   = (const float*)d_in[0];
    const void*  ei  = d_in[1];
    const float* W1  = (const float*)d_in[2];
    const float* b1  = (const float*)d_in[3];
    const float* W2  = (const float*)d_in[4];
    const float* b2  = (const float*)d_in[5];
    const float* Wm1 = (const float*)d_in[6];
    const float* bm1 = (const float*)d_in[7];
    const float* Wm2 = (const float*)d_in[8];
    const float* bm2 = (const float*)d_in[9];
    float* out = (float*)d_out;

    void *pcc = nullptr, *pa = nullptr, *pb = nullptr;
    void *pw1 = nullptr, *pw2 = nullptr, *pm1 = nullptr, *pm2 = nullptr;
    cudaGetSymbolAddress(&pcc, g_cc);
    cudaGetSymbolAddress(&pa, g_bufA);
    cudaGetSymbolAddress(&pb, g_bufB);
    cudaGetSymbolAddress(&pw1, g_Wt1);
    cudaGetSymbolAddress(&pw2, g_Wt2);
    cudaGetSymbolAddress(&pm1, g_Wtm1);
    cudaGetSymbolAddress(&pm2, g_Wtm2);
    __half2* bufA = (__half2*)pa;
    __half2* bufB = (__half2*)pb;
    const __half* Wt1  = (const __half*)pw1;
    const __half* Wt2  = (const __half*)pw2;
    const __half* Wtm1 = (const __half*)pm1;
    const __half* Wtm2 = (const __half*)pm2;

    cudaMemsetAsync(pcc, 0, (2 * NN + 4) * sizeof(int));

    k_cvtx <<<3125, 256>>>(x, bufA);                                        // 1
    k_wprep<<<4, 256>>>(W1, W2, Wm1, Wm2);                                  // 2
    k_gemmTC<8, false, false, false><<<GEMMG, 256>>>((const __half*)bufA, Wt1, nullptr, bufB);   // 3
    k_csr <<<CSRG, CSRT>>>(ei);                                             // 4: PROFILED
    k_agg<true><<<3125, 256>>>(bufB, b1, bufA);                             // 5
    k_gemmTC<8, false, false, false><<<GEMMG, 256>>>((const __half*)bufA, Wt2, nullptr, bufB);   // 6
    k_agg<false><<<3125, 256>>>(bufB, b2, bufA);                            // 7
    k_gemmTC<8, true, true, false><<<GEMMG, 256>>>((const __half*)bufA, Wtm1, bm1, bufB);        // 8
    k_gemmTC<5, true, false, true><<<GEMMG, 256>>>((const __half*)bufB, Wtm2, bm2, out);         // 9
}

// round 15
// speedup vs baseline: 1.2516x; 1.1125x over previous
#include <cuda_runtime.h>
#include <cuda_fp16.h>

#define NN 100000
#define EE 1000000
#define CC 64
#define OUTC 40
#define NB 98          // ceil(NN/1024)
#define E4 (EE/4)
#define CSRG 592       // resident grid: 148 SMs x 8 blocks guaranteed by launch_bounds
#define CSRT 256
#define NTILES 6250    // NN/16
#define GEMMG 782      // ceil(NTILES/8) -> 1 tile per warp

typedef unsigned long long ull;

// ---------------- device scratch ----------------
__device__ int            g_cc[NN + 4];    // [0,NN) counts ; [NN] barrier ; [NN+1] offset ctr
__device__ int            g_rowptr[NN];    // ABSOLUTE row start
__device__ float          g_dinv[NN];      // rsqrt(deg+1)
__device__ unsigned short g_pos[EE];       // position of edge within its dst row
__device__ int2           g_edge[EE];      // {src*8 (uint4 idx), bitcast(norm)} grouped by dst
__device__ __half2        g_bufA[NN * CC / 2];
__device__ __half2        g_bufB[NN * CC / 2];
__device__ __half         g_Wt1[CC * CC];  // transposed fp16 weights [n][k]
__device__ __half         g_Wt2[CC * CC];
__device__ __half         g_Wtm1[CC * CC];
__device__ __half         g_Wtm2[OUTC * CC];

// ---------------- prep: x fp32->fp16 rows ----------------
__global__ __launch_bounds__(256)
void k_cvtx(const float* __restrict__ x, __half2* __restrict__ out) {
    int i = blockIdx.x * 256 + threadIdx.x;   // one uint4 (8 halfs) per thread
    const float4* x4 = (const float4*)x;
    float4 f0 = x4[2 * i], f1 = x4[2 * i + 1];
    __half2 h0 = __floats2half2_rn(f0.x, f0.y);
    __half2 h1 = __floats2half2_rn(f0.z, f0.w);
    __half2 h2 = __floats2half2_rn(f1.x, f1.y);
    __half2 h3 = __floats2half2_rn(f1.z, f1.w);
    uint4 o;
    o.x = *(unsigned*)&h0; o.y = *(unsigned*)&h1;
    o.z = *(unsigned*)&h2; o.w = *(unsigned*)&h3;
    ((uint4*)out)[i] = o;
}

// ---------------- prep: weight transpose fp32->fp16 ----------------
__global__ __launch_bounds__(256)
void k_wprep(const float* __restrict__ W1, const float* __restrict__ W2,
             const float* __restrict__ Wm1, const float* __restrict__ Wm2) {
    int which = blockIdx.x, tid = threadIdx.x;
    if (which < 3) {
        const float* W = (which == 0) ? W1 : (which == 1) ? W2 : Wm1;
        __half* Wt = (which == 0) ? g_Wt1 : (which == 1) ? g_Wt2 : g_Wtm1;
        for (int i = tid; i < CC * CC; i += 256) {
            int n = i >> 6, k = i & 63;
            Wt[i] = __float2half(W[k * CC + n]);
        }
    } else {
        for (int i = tid; i < OUTC * CC; i += 256) {
            int n = i >> 6, k = i & 63;
            g_Wtm2[i] = __float2half(Wm2[k * OUTC + n]);
        }
    }
}

// ---------------- fused CSR build: hist(+pos) -> scan -> fill ----------------
__device__ __forceinline__ void gsync(int target) {
    __threadfence();
    __syncthreads();
    if (threadIdx.x == 0) {
        atomicAdd(&g_cc[NN], 1);
        while (atomicAdd(&g_cc[NN], 0) < target) __nanosleep(64);
        __threadfence();
    }
    __syncthreads();
}

__device__ __forceinline__ void fill_one(int s, int d, int pos) {
    float nm = g_dinv[s] * g_dinv[d];
    g_edge[g_rowptr[d] + pos] = make_int2(s * 8, __float_as_int(nm));
}

__global__ __launch_bounds__(CSRT, 8)
void k_csr(const void* __restrict__ ei) {
    __shared__ int s_is64;
    __shared__ int s_scan[CSRT];
    __shared__ int s_off;
    int tid = threadIdx.x, bid = blockIdx.x;

    if (tid == 0) {
        const long long* p = (const long long*)ei;
        int ok = 1;
#pragma unroll
        for (int i = 0; i < 16; i++) { long long v = p[i]; if (v < 0 || v >= NN) ok = 0; }
        s_is64 = ok;
    }
    __syncthreads();
    int is64 = s_is64;

    // Phase A: histogram; atomic return IS the within-row position -> coalesced scratch
    for (int i = bid * CSRT + tid; i < E4; i += CSRG * CSRT) {
        int p0, p1, p2, p3;
        if (!is64) {
            int4 d = ((const int4*)ei)[E4 + i];
            p0 = atomicAdd(&g_cc[d.x], 1);
            p1 = atomicAdd(&g_cc[d.y], 1);
            p2 = atomicAdd(&g_cc[d.z], 1);
            p3 = atomicAdd(&g_cc[d.w], 1);
        } else {
            const long long* p = (const long long*)ei;
            p0 = atomicAdd(&g_cc[(int)p[EE + 4 * i + 0]], 1);
            p1 = atomicAdd(&g_cc[(int)p[EE + 4 * i + 1]], 1);
            p2 = atomicAdd(&g_cc[(int)p[EE + 4 * i + 2]], 1);
            p3 = atomicAdd(&g_cc[(int)p[EE + 4 * i + 3]], 1);
        }
        ((ushort4*)g_pos)[i] = make_ushort4((unsigned short)p0, (unsigned short)p1,
                                            (unsigned short)p2, (unsigned short)p3);
    }
    gsync(CSRG);

    // Phase B: per-1024-node scan; block offset via global atomic -> ABSOLUTE rowptr
    if (bid < NB) {
        int base = bid * 1024 + tid * 4;
        int c0 = 0, c1 = 0, c2 = 0, c3 = 0;
        if (base + 0 < NN) c0 = g_cc[base + 0];
        if (base + 1 < NN) c1 = g_cc[base + 1];
        if (base + 2 < NN) c2 = g_cc[base + 2];
        if (base + 3 < NN) c3 = g_cc[base + 3];
        if (base + 0 < NN) g_dinv[base + 0] = rsqrtf((float)c0 + 1.0f);
        if (base + 1 < NN) g_dinv[base + 1] = rsqrtf((float)c1 + 1.0f);
        if (base + 2 < NN) g_dinv[base + 2] = rsqrtf((float)c2 + 1.0f);
        if (base + 3 < NN) g_dinv[base + 3] = rsqrtf((float)c3 + 1.0f);
        int v = c0 + c1 + c2 + c3;
        s_scan[tid] = v;
        __syncthreads();
        for (int off = 1; off < CSRT; off <<= 1) {
            int t2 = (tid >= off) ? s_scan[tid - off] : 0;
            __syncthreads();
            s_scan[tid] += t2;
            __syncthreads();
        }
        int incl = s_scan[tid];
        int excl = incl - v;
        if (tid == CSRT - 1) s_off = atomicAdd(&g_cc[NN + 1], incl);
        __syncthreads();
        int boff = s_off;
        if (base + 0 < NN) g_rowptr[base + 0] = boff + excl;
        if (base + 1 < NN) g_rowptr[base + 1] = boff + excl + c0;
        if (base + 2 < NN) g_rowptr[base + 2] = boff + excl + c0 + c1;
        if (base + 3 < NN) g_rowptr[base + 3] = boff + excl + c0 + c1 + c2;
    }
    gsync(2 * CSRG);

    // Phase C: fill edge records (no atomics; address = rowptr[d] + saved pos)
    for (int i = bid * CSRT + tid; i < E4; i += CSRG * CSRT) {
        ushort4 p = ((const ushort4*)g_pos)[i];
        if (!is64) {
            int4 s4 = ((const int4*)ei)[i];
            int4 d4 = ((const int4*)ei)[E4 + i];
            fill_one(s4.x, d4.x, p.x); fill_one(s4.y, d4.y, p.y);
            fill_one(s4.z, d4.z, p.z); fill_one(s4.w, d4.w, p.w);
        } else {
            const long long* q = (const long long*)ei;
            fill_one((int)q[4 * i + 0], (int)q[EE + 4 * i + 0], p.x);
            fill_one((int)q[4 * i + 1], (int)q[EE + 4 * i + 1], p.y);
            fill_one((int)q[4 * i + 2], (int)q[EE + 4 * i + 2], p.z);
            fill_one((int)q[4 * i + 3], (int)q[EE + 4 * i + 3], p.w);
        }
    }
}

// ---------------- tensor-core GEMM with smem + ldmatrix ----------------
__device__ __forceinline__ unsigned scvt(const void* p) {
    return (unsigned)__cvta_generic_to_shared(p);
}
__device__ __forceinline__ void ldsm4(unsigned& r0, unsigned& r1, unsigned& r2,
                                      unsigned& r3, unsigned addr) {
    asm volatile("ldmatrix.sync.aligned.m8n8.x4.shared.b16 {%0,%1,%2,%3}, [%4];"
                 : "=r"(r0), "=r"(r1), "=r"(r2), "=r"(r3) : "r"(addr));
}
__device__ __forceinline__ void ldsm2(unsigned& r0, unsigned& r1, unsigned addr) {
    asm volatile("ldmatrix.sync.aligned.m8n8.x2.shared.b16 {%0,%1}, [%2];"
                 : "=r"(r0), "=r"(r1) : "r"(addr));
}
__device__ __forceinline__ void mma16816(float c[4], unsigned a0, unsigned a1,
                                         unsigned a2, unsigned a3,
                                         unsigned b0, unsigned b1) {
    asm volatile(
        "mma.sync.aligned.m16n8k16.row.col.f32.f16.f16.f32 "
        "{%0,%1,%2,%3},{%4,%5,%6,%7},{%8,%9},{%0,%1,%2,%3};"
        : "+f"(c[0]), "+f"(c[1]), "+f"(c[2]), "+f"(c[3])
        : "r"(a0), "r"(a1), "r"(a2), "r"(a3), "r"(b0), "r"(b1));
}

// out[N, NT*8] = A[N,64](f16) @ Wt^T ; f32 accum. One 16-row tile per warp.
template <int NT, bool BIAS, bool RELU, bool OUTF32>
__global__ __launch_bounds__(256)
void k_gemmTC(const __half* __restrict__ A, const __half* __restrict__ Wt,
              const float* __restrict__ bias, void* __restrict__ outv) {
    const int NCOLS = NT * 8;
    __shared__ uint4 Bs[NT * 8 * 8];      // NT*8 rows x 8 swizzled 16B chunks
    __shared__ uint4 As[8][128];          // per-warp 16 rows x 8 swizzled chunks
    int tid = threadIdx.x, lane = tid & 31, wid = tid >> 5;

    const uint4* W4 = (const uint4*)Wt;
    for (int i = tid; i < NT * 64; i += 256) {
        int r = i >> 3, c = i & 7;
        Bs[r * 8 + (c ^ (r & 7))] = W4[i];
    }
    __syncthreads();

    int tile = blockIdx.x * 8 + wid;
    if (tile >= NTILES) return;

    const uint4* A4 = (const uint4*)(A + (size_t)tile * 16 * CC);
#pragma unroll
    for (int j = 0; j < 4; j++) {
        int i = j * 32 + lane;
        int r = i >> 3, c = i & 7;
        As[wid][r * 8 + (c ^ (r & 7))] = A4[i];
    }
    __syncwarp();

    int ri = lane & 7, m = lane >> 3;
    float c_[NT][4];
#pragma unroll
    for (int nt = 0; nt < NT; nt++) { c_[nt][0] = c_[nt][1] = c_[nt][2] = c_[nt][3] = 0.f; }

#pragma unroll
    for (int ks = 0; ks < 4; ks++) {
        int ar = (m & 1) ? (8 + ri) : ri;
        int ac = 2 * ks + (m >> 1);
        unsigned a0, a1, a2, a3;
        ldsm4(a0, a1, a2, a3, scvt(&As[wid][ar * 8 + (ac ^ (ar & 7))]));

        unsigned b[NT][2];
#pragma unroll
        for (int ntp = 0; ntp < NT / 2; ntp++) {
            int br = 16 * ntp + ((m >> 1) ? 8 : 0) + ri;
            int bc = 2 * ks + (m & 1);
            unsigned r0, r1, r2, r3;
            ldsm4(r0, r1, r2, r3, scvt(&Bs[br * 8 + (bc ^ (br & 7))]));
            b[2 * ntp][0] = r0; b[2 * ntp][1] = r1;
            b[2 * ntp + 1][0] = r2; b[2 * ntp + 1][1] = r3;
        }
        if (NT & 1) {
            int m2 = m & 1;
            int br = (NT - 1) * 8 + ri;
            int bc = 2 * ks + m2;
            unsigned r0, r1;
            ldsm2(r0, r1, scvt(&Bs[br * 8 + (bc ^ (br & 7))]));
            b[NT - 1][0] = r0; b[NT - 1][1] = r1;
        }

#pragma unroll
        for (int nt = 0; nt < NT; nt++)
            mma16816(c_[nt], a0, a1, a2, a3, b[nt][0], b[nt][1]);
    }

    int g = lane >> 2, t = lane & 3;
    int r0 = tile * 16 + g;
#pragma unroll
    for (int nt = 0; nt < NT; nt++) {
        int col = nt * 8 + 2 * t;
        float c0 = c_[nt][0], c1 = c_[nt][1], c2 = c_[nt][2], c3 = c_[nt][3];
        if (BIAS) {
            float bb0 = __ldg(bias + col), bb1 = __ldg(bias + col + 1);
            c0 += bb0; c1 += bb1; c2 += bb0; c3 += bb1;
        }
        if (RELU) {
            c0 = fmaxf(c0, 0.f); c1 = fmaxf(c1, 0.f);
            c2 = fmaxf(c2, 0.f); c3 = fmaxf(c3, 0.f);
        }
        if (OUTF32) {
            float* o = (float*)outv;
            *(float2*)(o + (size_t)r0 * NCOLS + col)       = make_float2(c0, c1);
            *(float2*)(o + (size_t)(r0 + 8) * NCOLS + col) = make_float2(c2, c3);
        } else {
            __half* o = (__half*)outv;
            *(__half2*)(o + (size_t)r0 * NCOLS + col)       = __floats2half2_rn(c0, c1);
            *(__half2*)(o + (size_t)(r0 + 8) * NCOLS + col) = __floats2half2_rn(c2, c3);
        }
    }
}

// ---------------- aggregation: 4 nodes/warp, 8 lanes/node (R12 form) ----------------
template <bool RELU>
__global__ __launch_bounds__(256)
void k_agg(const __half2* __restrict__ hf, const float* __restrict__ bias,
           __half2* __restrict__ out) {
    const uint4* hf4 = (const uint4*)hf;
    int node = blockIdx.x * 32 + (threadIdx.x >> 3);
    int l = threadIdx.x & 7;

    int deg = g_cc[node];
    float self = __frcp_rn((float)deg + 1.0f);   // dinv^2

    float a0, a1, a2, a3, a4, a5, a6, a7;
    {
        uint4 v = hf4[node * 8 + l];
        const __half2* hp = (const __half2*)&v;
        float2 f0 = __half22float2(hp[0]), f1 = __half22float2(hp[1]);
        float2 f2 = __half22float2(hp[2]), f3 = __half22float2(hp[3]);
        a0 = f0.x * self; a1 = f0.y * self;
        a2 = f1.x * self; a3 = f1.y * self;
        a4 = f2.x * self; a5 = f2.y * self;
        a6 = f3.x * self; a7 = f3.y * self;
    }

    int beg = g_rowptr[node];
    int end = beg + deg;

    int e = beg;
    for (; e + 1 < end; e += 2) {
        int2 m0 = g_edge[e], m1 = g_edge[e + 1];
        uint4 v0 = hf4[m0.x + l];
        uint4 v1 = hf4[m1.x + l];
        float n0 = __int_as_float(m0.y);
        float n1 = __int_as_float(m1.y);
        {
            const __half2* hp = (const __half2*)&v0;
            float2 f0 = __half22float2(hp[0]), f1 = __half22float2(hp[1]);
            float2 f2 = __half22float2(hp[2]), f3 = __half22float2(hp[3]);
            a0 = fmaf(f0.x, n0, a0); a1 = fmaf(f0.y, n0, a1);
            a2 = fmaf(f1.x, n0, a2); a3 = fmaf(f1.y, n0, a3);
            a4 = fmaf(f2.x, n0, a4); a5 = fmaf(f2.y, n0, a5);
            a6 = fmaf(f3.x, n0, a6); a7 = fmaf(f3.y, n0, a7);
        }
        {
            const __half2* hp = (const __half2*)&v1;
            float2 f0 = __half22float2(hp[0]), f1 = __half22float2(hp[1]);
            float2 f2 = __half22float2(hp[2]), f3 = __half22float2(hp[3]);
            a0 = fmaf(f0.x, n1, a0); a1 = fmaf(f0.y, n1, a1);
            a2 = fmaf(f1.x, n1, a2); a3 = fmaf(f1.y, n1, a3);
            a4 = fmaf(f2.x, n1, a4); a5 = fmaf(f2.y, n1, a5);
            a6 = fmaf(f3.x, n1, a6); a7 = fmaf(f3.y, n1, a7);
        }
    }
    if (e < end) {
        int2 m = g_edge[e];
        uint4 v = hf4[m.x + l];
        float nm = __int_as_float(m.y);
        const __half2* hp = (const __half2*)&v;
        float2 f0 = __half22float2(hp[0]), f1 = __half22float2(hp[1]);
        float2 f2 = __half22float2(hp[2]), f3 = __half22float2(hp[3]);
        a0 = fmaf(f0.x, nm, a0); a1 = fmaf(f0.y, nm, a1);
        a2 = fmaf(f1.x, nm, a2); a3 = fmaf(f1.y, nm, a3);
        a4 = fmaf(f2.x, nm, a4); a5 = fmaf(f2.y, nm, a5);
        a6 = fmaf(f3.x, nm, a6); a7 = fmaf(f3.y, nm, a7);
    }

    const float4* b4 = (const float4*)(bias + l * 8);
    float4 bA = b4[0], bB = b4[1];
    a0 += bA.x; a1 += bA.y; a2 += bA.z; a3 += bA.w;
    a4 += bB.x; a5 += bB.y; a6 += bB.z; a7 += bB.w;
    if (RELU) {
        a0 = fmaxf(a0, 0.f); a1 = fmaxf(a1, 0.f);
        a2 = fmaxf(a2, 0.f); a3 = fmaxf(a3, 0.f);
        a4 = fmaxf(a4, 0.f); a5 = fmaxf(a5, 0.f);
        a6 = fmaxf(a6, 0.f); a7 = fmaxf(a7, 0.f);
    }
    __half2 h0 = __floats2half2_rn(a0, a1);
    __half2 h1 = __floats2half2_rn(a2, a3);
    __half2 h2 = __floats2half2_rn(a4, a5);
    __half2 h3 = __floats2half2_rn(a6, a7);
    uint4 o;
    o.x = *(unsigned*)&h0; o.y = *(unsigned*)&h1;
    o.z = *(unsigned*)&h2; o.w = *(unsigned*)&h3;
    ((uint4*)out)[node * 8 + l] = o;
}

// ---------------- launcher ----------------
extern "C" void kernel_launch(void* const* d_in, const int* in_sizes, int n_in,
                              void* d_out, int out_size) {
    const float* x   = (const float*)d_in[0];
    const void*  ei  = d_in[1];
    const float* W1  = (const float*)d_in[2];
    const float* b1  = (const float*)d_in[3];
    const float* W2  = (const float*)d_in[4];
    const float* b2  = (const float*)d_in[5];
    const float* Wm1 = (const float*)d_in[6];
    const float* bm1 = (const float*)d_in[7];
    const float* Wm2 = (const float*)d_in[8];
    const float* bm2 = (const float*)d_in[9];
    float* out = (float*)d_out;

    void *pcc = nullptr, *pa = nullptr, *pb = nullptr;
    void *pw1 = nullptr, *pw2 = nullptr, *pm1 = nullptr, *pm2 = nullptr;
    cudaGetSymbolAddress(&pcc, g_cc);
    cudaGetSymbolAddress(&pa, g_bufA);
    cudaGetSymbolAddress(&pb, g_bufB);
    cudaGetSymbolAddress(&pw1, g_Wt1);
    cudaGetSymbolAddress(&pw2, g_Wt2);
    cudaGetSymbolAddress(&pm1, g_Wtm1);
    cudaGetSymbolAddress(&pm2, g_Wtm2);
    __half2* bufA = (__half2*)pa;
    __half2* bufB = (__half2*)pb;
    const __half* Wt1  = (const __half*)pw1;
    const __half* Wt2  = (const __half*)pw2;
    const __half* Wtm1 = (const __half*)pm1;
    const __half* Wtm2 = (const __half*)pm2;

    // fork-join: CSR on a side stream, concurrent with cvtx/wprep/gemm1
    cudaStream_t s2;
    cudaStreamCreateWithFlags(&s2, cudaStreamNonBlocking);
    cudaEvent_t evFork, evJoin;
    cudaEventCreateWithFlags(&evFork, cudaEventDisableTiming);
    cudaEventCreateWithFlags(&evJoin, cudaEventDisableTiming);

    cudaMemsetAsync(pcc, 0, (NN + 4) * sizeof(int));
    cudaEventRecord(evFork, 0);
    cudaStreamWaitEvent(s2, evFork, 0);
    k_csr<<<CSRG, CSRT, 0, s2>>>(ei);                                       // side stream
    cudaEventRecord(evJoin, s2);

    k_cvtx <<<3125, 256>>>(x, bufA);                                        // main stream
    k_wprep<<<4, 256>>>(W1, W2, Wm1, Wm2);
    k_gemmTC<8, false, false, false><<<GEMMG, 256>>>((const __half*)bufA, Wt1, nullptr, bufB);

    cudaStreamWaitEvent(0, evJoin, 0);                                      // join
    k_agg<true><<<3125, 256>>>(bufB, b1, bufA);
    k_gemmTC<8, false, false, false><<<GEMMG, 256>>>((const __half*)bufA, Wt2, nullptr, bufB);
    k_agg<false><<<3125, 256>>>(bufB, b2, bufA);
    k_gemmTC<8, true, true, false><<<GEMMG, 256>>>((const __half*)bufA, Wtm1, bm1, bufB);
    k_gemmTC<5, true, false, true><<<GEMMG, 256>>>((const __half*)bufB, Wtm2, bm2, out);

    cudaStreamDestroy(s2);
    cudaEventDestroy(evFork);
    cudaEventDestroy(evJoin);
}

// round 17
// speedup vs baseline: 1.3006x; 1.0392x over previous
#include <cuda_runtime.h>
#include <cuda_fp16.h>

#define NN 100000
#define EE 1000000
#define CC 64
#define OUTC 40
#define NB 98          // ceil(NN/1024)
#define E4 (EE/4)
#define CSRG 592       // resident grid: 148 SMs x 8 blocks guaranteed by launch_bounds
#define CSRT 256
#define NTILES 6250    // NN/16
#define GEMMG 782      // ceil(NTILES/8) -> 1 tile per warp

typedef unsigned long long ull;

// ---------------- device scratch ----------------
__device__ int            g_cc[NN + 4];    // [0,NN) counts ; [NN] barrier ; [NN+1] offset ctr
__device__ int            g_rowptr[NN];    // ABSOLUTE row start
__device__ float          g_dinv[NN];      // rsqrt(deg+1)
__device__ unsigned short g_pos[EE];       // position of edge within its dst row
__device__ int2           g_edge[EE];      // {src*8 (uint4 idx), bitcast(norm)} grouped by dst
__device__ __half2        g_bufA[NN * CC / 2];
__device__ __half2        g_bufB[NN * CC / 2];
__device__ __half         g_Wt1[CC * CC];  // transposed fp16 weights [n][k]
__device__ __half         g_Wt2[CC * CC];
__device__ __half         g_Wtm1[CC * CC];
__device__ __half         g_Wtm2[OUTC * CC];

// ---------------- fused prep: x fp32->fp16 rows + weight transpose ----------------
__global__ __launch_bounds__(256)
void k_prepall(const float* __restrict__ x, __half2* __restrict__ out,
               const float* __restrict__ W1, const float* __restrict__ W2,
               const float* __restrict__ Wm1, const float* __restrict__ Wm2) {
    int b = blockIdx.x, tid = threadIdx.x;
    if (b < 3125) {
        int i = b * 256 + tid;                 // one uint4 (8 halfs) per thread
        const float4* x4 = (const float4*)x;
        float4 f0 = x4[2 * i], f1 = x4[2 * i + 1];
        __half2 h0 = __floats2half2_rn(f0.x, f0.y);
        __half2 h1 = __floats2half2_rn(f0.z, f0.w);
        __half2 h2 = __floats2half2_rn(f1.x, f1.y);
        __half2 h3 = __floats2half2_rn(f1.z, f1.w);
        uint4 o;
        o.x = *(unsigned*)&h0; o.y = *(unsigned*)&h1;
        o.z = *(unsigned*)&h2; o.w = *(unsigned*)&h3;
        ((uint4*)out)[i] = o;
    } else {
        int which = b - 3125;
        if (which < 3) {
            const float* W = (which == 0) ? W1 : (which == 1) ? W2 : Wm1;
            __half* Wt = (which == 0) ? g_Wt1 : (which == 1) ? g_Wt2 : g_Wtm1;
            for (int i = tid; i < CC * CC; i += 256) {
                int n = i >> 6, k = i & 63;
                Wt[i] = __float2half(W[k * CC + n]);
            }
        } else {
            for (int i = tid; i < OUTC * CC; i += 256) {
                int n = i >> 6, k = i & 63;
                g_Wtm2[i] = __float2half(Wm2[k * OUTC + n]);
            }
        }
    }
}

// ---------------- fused CSR build: hist(+pos) -> scan -> fill ----------------
__device__ __forceinline__ void gsync(int target) {
    __threadfence();
    __syncthreads();
    if (threadIdx.x == 0) {
        atomicAdd(&g_cc[NN], 1);
        while (atomicAdd(&g_cc[NN], 0) < target) __nanosleep(64);
        __threadfence();
    }
    __syncthreads();
}

__device__ __forceinline__ void fill_one(int s, int d, int pos) {
    float nm = g_dinv[s] * g_dinv[d];
    g_edge[g_rowptr[d] + pos] = make_int2(s * 8, __float_as_int(nm));
}

__global__ __launch_bounds__(CSRT, 8)
void k_csr(const void* __restrict__ ei) {
    __shared__ int s_is64;
    __shared__ int s_scan[CSRT];
    __shared__ int s_off;
    int tid = threadIdx.x, bid = blockIdx.x;

    if (tid == 0) {
        const long long* p = (const long long*)ei;
        int ok = 1;
#pragma unroll
        for (int i = 0; i < 16; i++) { long long v = p[i]; if (v < 0 || v >= NN) ok = 0; }
        s_is64 = ok;
    }
    __syncthreads();
    int is64 = s_is64;

    // Phase A: histogram; atomic return IS the within-row position -> coalesced scratch
    for (int i = bid * CSRT + tid; i < E4; i += CSRG * CSRT) {
        int p0, p1, p2, p3;
        if (!is64) {
            int4 d = ((const int4*)ei)[E4 + i];
            p0 = atomicAdd(&g_cc[d.x], 1);
            p1 = atomicAdd(&g_cc[d.y], 1);
            p2 = atomicAdd(&g_cc[d.z], 1);
            p3 = atomicAdd(&g_cc[d.w], 1);
        } else {
            const long long* p = (const long long*)ei;
            p0 = atomicAdd(&g_cc[(int)p[EE + 4 * i + 0]], 1);
            p1 = atomicAdd(&g_cc[(int)p[EE + 4 * i + 1]], 1);
            p2 = atomicAdd(&g_cc[(int)p[EE + 4 * i + 2]], 1);
            p3 = atomicAdd(&g_cc[(int)p[EE + 4 * i + 3]], 1);
        }
        ((ushort4*)g_pos)[i] = make_ushort4((unsigned short)p0, (unsigned short)p1,
                                            (unsigned short)p2, (unsigned short)p3);
    }
    gsync(CSRG);

    // Phase B: per-1024-node scan; block offset via global atomic -> ABSOLUTE rowptr
    if (bid < NB) {
        int base = bid * 1024 + tid * 4;
        int c0 = 0, c1 = 0, c2 = 0, c3 = 0;
        if (base + 0 < NN) c0 = g_cc[base + 0];
        if (base + 1 < NN) c1 = g_cc[base + 1];
        if (base + 2 < NN) c2 = g_cc[base + 2];
        if (base + 3 < NN) c3 = g_cc[base + 3];
        if (base + 0 < NN) g_dinv[base + 0] = rsqrtf((float)c0 + 1.0f);
        if (base + 1 < NN) g_dinv[base + 1] = rsqrtf((float)c1 + 1.0f);
        if (base + 2 < NN) g_dinv[base + 2] = rsqrtf((float)c2 + 1.0f);
        if (base + 3 < NN) g_dinv[base + 3] = rsqrtf((float)c3 + 1.0f);
        int v = c0 + c1 + c2 + c3;
        s_scan[tid] = v;
        __syncthreads();
        for (int off = 1; off < CSRT; off <<= 1) {
            int t2 = (tid >= off) ? s_scan[tid - off] : 0;
            __syncthreads();
            s_scan[tid] += t2;
            __syncthreads();
        }
        int incl = s_scan[tid];
        int excl = incl - v;
        if (tid == CSRT - 1) s_off = atomicAdd(&g_cc[NN + 1], incl);
        __syncthreads();
        int boff = s_off;
        if (base + 0 < NN) g_rowptr[base + 0] = boff + excl;
        if (base + 1 < NN) g_rowptr[base + 1] = boff + excl + c0;
        if (base + 2 < NN) g_rowptr[base + 2] = boff + excl + c0 + c1;
        if (base + 3 < NN) g_rowptr[base + 3] = boff + excl + c0 + c1 + c2;
    }
    gsync(2 * CSRG);

    // Phase C: fill edge records (no atomics; address = rowptr[d] + saved pos)
    for (int i = bid * CSRT + tid; i < E4; i += CSRG * CSRT) {
        ushort4 p = ((const ushort4*)g_pos)[i];
        if (!is64) {
            int4 s4 = ((const int4*)ei)[i];
            int4 d4 = ((const int4*)ei)[E4 + i];
            fill_one(s4.x, d4.x, p.x); fill_one(s4.y, d4.y, p.y);
            fill_one(s4.z, d4.z, p.z); fill_one(s4.w, d4.w, p.w);
        } else {
            const long long* q = (const long long*)ei;
            fill_one((int)q[4 * i + 0], (int)q[EE + 4 * i + 0], p.x);
            fill_one((int)q[4 * i + 1], (int)q[EE + 4 * i + 1], p.y);
            fill_one((int)q[4 * i + 2], (int)q[EE + 4 * i + 2], p.z);
            fill_one((int)q[4 * i + 3], (int)q[EE + 4 * i + 3], p.w);
        }
    }
}

// ---------------- tensor-core GEMM with smem + ldmatrix ----------------
__device__ __forceinline__ unsigned scvt(const void* p) {
    return (unsigned)__cvta_generic_to_shared(p);
}
__device__ __forceinline__ void ldsm4(unsigned& r0, unsigned& r1, unsigned& r2,
                                      unsigned& r3, unsigned addr) {
    asm volatile("ldmatrix.sync.aligned.m8n8.x4.shared.b16 {%0,%1,%2,%3}, [%4];"
                 : "=r"(r0), "=r"(r1), "=r"(r2), "=r"(r3) : "r"(addr));
}
__device__ __forceinline__ void ldsm2(unsigned& r0, unsigned& r1, unsigned addr) {
    asm volatile("ldmatrix.sync.aligned.m8n8.x2.shared.b16 {%0,%1}, [%2];"
                 : "=r"(r0), "=r"(r1) : "r"(addr));
}
__device__ __forceinline__ void mma16816(float c[4], unsigned a0, unsigned a1,
                                         unsigned a2, unsigned a3,
                                         unsigned b0, unsigned b1) {
    asm volatile(
        "mma.sync.aligned.m16n8k16.row.col.f32.f16.f16.f32 "
        "{%0,%1,%2,%3},{%4,%5,%6,%7},{%8,%9},{%0,%1,%2,%3};"
        : "+f"(c[0]), "+f"(c[1]), "+f"(c[2]), "+f"(c[3])
        : "r"(a0), "r"(a1), "r"(a2), "r"(a3), "r"(b0), "r"(b1));
}

// out[N, NT*8] = A[N,64](f16) @ Wt^T ; f32 accum. One 16-row tile per warp.
template <int NT, bool BIAS, bool RELU, bool OUTF32>
__global__ __launch_bounds__(256)
void k_gemmTC(const __half* __restrict__ A, const __half* __restrict__ Wt,
              const float* __restrict__ bias, void* __restrict__ outv) {
    const int NCOLS = NT * 8;
    __shared__ uint4 Bs[NT * 8 * 8];      // NT*8 rows x 8 swizzled 16B chunks
    __shared__ uint4 As[8][128];          // per-warp 16 rows x 8 swizzled chunks
    int tid = threadIdx.x, lane = tid & 31, wid = tid >> 5;

    const uint4* W4 = (const uint4*)Wt;
    for (int i = tid; i < NT * 64; i += 256) {
        int r = i >> 3, c = i & 7;
        Bs[r * 8 + (c ^ (r & 7))] = W4[i];
    }
    __syncthreads();

    int tile = blockIdx.x * 8 + wid;
    if (tile >= NTILES) return;

    const uint4* A4 = (const uint4*)(A + (size_t)tile * 16 * CC);
#pragma unroll
    for (int j = 0; j < 4; j++) {
        int i = j * 32 + lane;
        int r = i >> 3, c = i & 7;
        As[wid][r * 8 + (c ^ (r & 7))] = A4[i];
    }
    __syncwarp();

    int ri = lane & 7, m = lane >> 3;
    float c_[NT][4];
#pragma unroll
    for (int nt = 0; nt < NT; nt++) { c_[nt][0] = c_[nt][1] = c_[nt][2] = c_[nt][3] = 0.f; }

#pragma unroll
    for (int ks = 0; ks < 4; ks++) {
        int ar = (m & 1) ? (8 + ri) : ri;
        int ac = 2 * ks + (m >> 1);
        unsigned a0, a1, a2, a3;
        ldsm4(a0, a1, a2, a3, scvt(&As[wid][ar * 8 + (ac ^ (ar & 7))]));

        unsigned b[NT][2];
#pragma unroll
        for (int ntp = 0; ntp < NT / 2; ntp++) {
            int br = 16 * ntp + ((m >> 1) ? 8 : 0) + ri;
            int bc = 2 * ks + (m & 1);
            unsigned r0, r1, r2, r3;
            ldsm4(r0, r1, r2, r3, scvt(&Bs[br * 8 + (bc ^ (br & 7))]));
            b[2 * ntp][0] = r0; b[2 * ntp][1] = r1;
            b[2 * ntp + 1][0] = r2; b[2 * ntp + 1][1] = r3;
        }
        if (NT & 1) {
            int m2 = m & 1;
            int br = (NT - 1) * 8 + ri;
            int bc = 2 * ks + m2;
            unsigned r0, r1;
            ldsm2(r0, r1, scvt(&Bs[br * 8 + (bc ^ (br & 7))]));
            b[NT - 1][0] = r0; b[NT - 1][1] = r1;
        }

#pragma unroll
        for (int nt = 0; nt < NT; nt++)
            mma16816(c_[nt], a0, a1, a2, a3, b[nt][0], b[nt][1]);
    }

    int g = lane >> 2, t = lane & 3;
    int r0 = tile * 16 + g;
#pragma unroll
    for (int nt = 0; nt < NT; nt++) {
        int col = nt * 8 + 2 * t;
        float c0 = c_[nt][0], c1 = c_[nt][1], c2 = c_[nt][2], c3 = c_[nt][3];
        if (BIAS) {
            float bb0 = __ldg(bias + col), bb1 = __ldg(bias + col + 1);
            c0 += bb0; c1 += bb1; c2 += bb0; c3 += bb1;
        }
        if (RELU) {
            c0 = fmaxf(c0, 0.f); c1 = fmaxf(c1, 0.f);
            c2 = fmaxf(c2, 0.f); c3 = fmaxf(c3, 0.f);
        }
        if (OUTF32) {
            float* o = (float*)outv;
            *(float2*)(o + (size_t)r0 * NCOLS + col)       = make_float2(c0, c1);
            *(float2*)(o + (size_t)(r0 + 8) * NCOLS + col) = make_float2(c2, c3);
        } else {
            __half* o = (__half*)outv;
            *(__half2*)(o + (size_t)r0 * NCOLS + col)       = __floats2half2_rn(c0, c1);
            *(__half2*)(o + (size_t)(r0 + 8) * NCOLS + col) = __floats2half2_rn(c2, c3);
        }
    }
}

// ---------------- aggregation: 4 nodes/warp, 8 lanes/node, unroll 4, plain FFMA ----------------
template <bool RELU>
__global__ __launch_bounds__(256)
void k_agg(const __half2* __restrict__ hf, const float* __restrict__ bias,
           __half2* __restrict__ out) {
    const uint4* hf4 = (const uint4*)hf;
    int node = blockIdx.x * 32 + (threadIdx.x >> 3);
    int l = threadIdx.x & 7;

    int deg = g_cc[node];
    float self = __frcp_rn((float)deg + 1.0f);   // dinv^2

    float a0, a1, a2, a3, a4, a5, a6, a7;
    {
        uint4 v = hf4[node * 8 + l];
        const __half2* hp = (const __half2*)&v;
        float2 f0 = __half22float2(hp[0]), f1 = __half22float2(hp[1]);
        float2 f2 = __half22float2(hp[2]), f3 = __half22float2(hp[3]);
        a0 = f0.x * self; a1 = f0.y * self;
        a2 = f1.x * self; a3 = f1.y * self;
        a4 = f2.x * self; a5 = f2.y * self;
        a6 = f3.x * self; a7 = f3.y * self;
    }

    int beg = g_rowptr[node];
    int end = beg + deg;

    int e = beg;
    // main loop: 4 edges per iter; metas via 4 independent int2 loads (8B-aligned);
    // 4 independent gathers in flight
    for (; e + 3 < end; e += 4) {
        int2 m0 = g_edge[e];
        int2 m1 = g_edge[e + 1];
        int2 m2 = g_edge[e + 2];
        int2 m3 = g_edge[e + 3];
        uint4 v0 = hf4[m0.x + l];
        uint4 v1 = hf4[m1.x + l];
        uint4 v2 = hf4[m2.x + l];
        uint4 v3 = hf4[m3.x + l];
        float n0 = __int_as_float(m0.y);
        float n1 = __int_as_float(m1.y);
        float n2 = __int_as_float(m2.y);
        float n3 = __int_as_float(m3.y);
        {
            const __half2* hp = (const __half2*)&v0;
            float2 f0 = __half22float2(hp[0]), f1 = __half22float2(hp[1]);
            float2 f2 = __half22float2(hp[2]), f3 = __half22float2(hp[3]);
            a0 = fmaf(f0.x, n0, a0); a1 = fmaf(f0.y, n0, a1);
            a2 = fmaf(f1.x, n0, a2); a3 = fmaf(f1.y, n0, a3);
            a4 = fmaf(f2.x, n0, a4); a5 = fmaf(f2.y, n0, a5);
            a6 = fmaf(f3.x, n0, a6); a7 = fmaf(f3.y, n0, a7);
        }
        {
            const __half2* hp = (const __half2*)&v1;
            float2 f0 = __half22float2(hp[0]), f1 = __half22float2(hp[1]);
            float2 f2 = __half22float2(hp[2]), f3 = __half22float2(hp[3]);
            a0 = fmaf(f0.x, n1, a0); a1 = fmaf(f0.y, n1, a1);
            a2 = fmaf(f1.x, n1, a2); a3 = fmaf(f1.y, n1, a3);
            a4 = fmaf(f2.x, n1, a4); a5 = fmaf(f2.y, n1, a5);
            a6 = fmaf(f3.x, n1, a6); a7 = fmaf(f3.y, n1, a7);
        }
        {
            const __half2* hp = (const __half2*)&v2;
            float2 f0 = __half22float2(hp[0]), f1 = __half22float2(hp[1]);
            float2 f2 = __half22float2(hp[2]), f3 = __half22float2(hp[3]);
            a0 = fmaf(f0.x, n2, a0); a1 = fmaf(f0.y, n2, a1);
            a2 = fmaf(f1.x, n2, a2); a3 = fmaf(f1.y, n2, a3);
            a4 = fmaf(f2.x, n2, a4); a5 = fmaf(f2.y, n2, a5);
            a6 = fmaf(f3.x, n2, a6); a7 = fmaf(f3.y, n2, a7);
        }
        {
            const __half2* hp = (const __half2*)&v3;
            float2 f0 = __half22float2(hp[0]), f1 = __half22float2(hp[1]);
            float2 f2 = __half22float2(hp[2]), f3 = __half22float2(hp[3]);
            a0 = fmaf(f0.x, n3, a0); a1 = fmaf(f0.y, n3, a1);
            a2 = fmaf(f1.x, n3, a2); a3 = fmaf(f1.y, n3, a3);
            a4 = fmaf(f2.x, n3, a4); a5 = fmaf(f2.y, n3, a5);
            a6 = fmaf(f3.x, n3, a6); a7 = fmaf(f3.y, n3, a7);
        }
    }
    for (; e < end; e++) {
        int2 m = g_edge[e];
        uint4 v = hf4[m.x + l];
        float nm = __int_as_float(m.y);
        const __half2* hp = (const __half2*)&v;
        float2 f0 = __half22float2(hp[0]), f1 = __half22float2(hp[1]);
        float2 f2 = __half22float2(hp[2]), f3 = __half22float2(hp[3]);
        a0 = fmaf(f0.x, nm, a0); a1 = fmaf(f0.y, nm, a1);
        a2 = fmaf(f1.x, nm, a2); a3 = fmaf(f1.y, nm, a3);
        a4 = fmaf(f2.x, nm, a4); a5 = fmaf(f2.y, nm, a5);
        a6 = fmaf(f3.x, nm, a6); a7 = fmaf(f3.y, nm, a7);
    }

    const float4* b4 = (const float4*)(bias + l * 8);
    float4 bA = b4[0], bB = b4[1];
    a0 += bA.x; a1 += bA.y; a2 += bA.z; a3 += bA.w;
    a4 += bB.x; a5 += bB.y; a6 += bB.z; a7 += bB.w;
    if (RELU) {
        a0 = fmaxf(a0, 0.f); a1 = fmaxf(a1, 0.f);
        a2 = fmaxf(a2, 0.f); a3 = fmaxf(a3, 0.f);
        a4 = fmaxf(a4, 0.f); a5 = fmaxf(a5, 0.f);
        a6 = fmaxf(a6, 0.f); a7 = fmaxf(a7, 0.f);
    }
    __half2 h0 = __floats2half2_rn(a0, a1);
    __half2 h1 = __floats2half2_rn(a2, a3);
    __half2 h2 = __floats2half2_rn(a4, a5);
    __half2 h3 = __floats2half2_rn(a6, a7);
    uint4 o;
    o.x = *(unsigned*)&h0; o.y = *(unsigned*)&h1;
    o.z = *(unsigned*)&h2; o.w = *(unsigned*)&h3;
    ((uint4*)out)[node * 8 + l] = o;
}

// ---------------- launcher ----------------
extern "C" void kernel_launch(void* const* d_in, const int* in_sizes, int n_in,
                              void* d_out, int out_size) {
    const float* x   = (const float*)d_in[0];
    const void*  ei  = d_in[1];
    const float* W1  = (const float*)d_in[2];
    const float* b1  = (const float*)d_in[3];
    const float* W2  = (const float*)d_in[4];
    const float* b2  = (const float*)d_in[5];
    const float* Wm1 = (const float*)d_in[6];
    const float* bm1 = (const float*)d_in[7];
    const float* Wm2 = (const float*)d_in[8];
    const float* bm2 = (const float*)d_in[9];
    float* out = (float*)d_out;

    void *pcc = nullptr, *pa = nullptr, *pb = nullptr;
    void *pw1 = nullptr, *pw2 = nullptr, *pm1 = nullptr, *pm2 = nullptr;
    cudaGetSymbolAddress(&pcc, g_cc);
    cudaGetSymbolAddress(&pa, g_bufA);
    cudaGetSymbolAddress(&pb, g_bufB);
    cudaGetSymbolAddress(&pw1, g_Wt1);
    cudaGetSymbolAddress(&pw2, g_Wt2);
    cudaGetSymbolAddress(&pm1, g_Wtm1);
    cudaGetSymbolAddress(&pm2, g_Wtm2);
    __half2* bufA = (__half2*)pa;
    __half2* bufB = (__half2*)pb;
    const __half* Wt1  = (const __half*)pw1;
    const __half* Wt2  = (const __half*)pw2;
    const __half* Wtm1 = (const __half*)pm1;
    const __half* Wtm2 = (const __half*)pm2;

    // fork-join: CSR on a side stream, concurrent with prepall/gemm1
    cudaStream_t s2;
    cudaStreamCreateWithFlags(&s2, cudaStreamNonBlocking);
    cudaEvent_t evFork, evJoin;
    cudaEventCreateWithFlags(&evFork, cudaEventDisableTiming);
    cudaEventCreateWithFlags(&evJoin, cudaEventDisableTiming);

    cudaMemsetAsync(pcc, 0, (NN + 4) * sizeof(int));
    cudaEventRecord(evFork, 0);
    cudaStreamWaitEvent(s2, evFork, 0);
    k_csr<<<CSRG, CSRT, 0, s2>>>(ei);                                       // 1 (side)
    cudaEventRecord(evJoin, s2);

    k_prepall<<<3129, 256>>>(x, bufA, W1, W2, Wm1, Wm2);                    // 2 (main)
    k_gemmTC<8, false, false, false><<<GEMMG, 256>>>((const __half*)bufA, Wt1, nullptr, bufB);   // 3

    cudaStreamWaitEvent(0, evJoin, 0);                                      // join
    k_agg<true><<<3125, 256>>>(bufB, b1, bufA);                             // 4: PROFILED
    k_gemmTC<8, false, false, false><<<GEMMG, 256>>>((const __half*)bufA, Wt2, nullptr, bufB);   // 5
    k_agg<false><<<3125, 256>>>(bufB, b2, bufA);                            // 6
    k_gemmTC<8, true, true, false><<<GEMMG, 256>>>((const __half*)bufA, Wtm1, bm1, bufB);        // 7
    k_gemmTC<5, true, false, true><<<GEMMG, 256>>>((const __half*)bufB, Wtm2, bm2, out);         // 8

    cudaStreamDestroy(s2);
    cudaEventDestroy(evFork);
    cudaEventDestroy(evJoin);
}